// round 2
// baseline (speedup 1.0000x reference)
#include <cuda_runtime.h>
#include <cuda_bf16.h>
#include <math.h>

// Problem constants
#define BI 4
#define TT 1024
#define CC 1024
#define HH 16
#define DD 64
#define LL 8
#define VV 32000

// Scratch buffers (static device globals — no allocation allowed)
__device__ float g_x  [BI * TT * CC];       // residual stream (16 MB)
__device__ float g_h  [BI * TT * CC];       // LN output       (16 MB)
__device__ float g_qkv[BI * TT * 3 * CC];   // qkv             (48 MB)
__device__ float g_y  [BI * TT * CC];       // attn out        (16 MB)
__device__ float g_mlp[BI * TT * 2 * CC];   // mlp hidden      (32 MB)
__device__ int   g_flags[BI * TT];          // is_resp flags

// ---------------------------------------------------------------------------
// Warp reduction helpers
// ---------------------------------------------------------------------------
__device__ __forceinline__ float warpSum(float v) {
    #pragma unroll
    for (int o = 16; o > 0; o >>= 1) v += __shfl_xor_sync(0xffffffffu, v, o);
    return v;
}
__device__ __forceinline__ float warpMax(float v) {
    #pragma unroll
    for (int o = 16; o > 0; o >>= 1) v = fmaxf(v, __shfl_xor_sync(0xffffffffu, v, o));
    return v;
}

// ---------------------------------------------------------------------------
// Dialog-positional flag prefix: flags[b,t] = any(idx[b,:t+1] == 2)
// ---------------------------------------------------------------------------
__global__ void flags_kernel(const int* __restrict__ idx) {
    int b = blockIdx.x;
    if (threadIdx.x == 0) {
        int f = 0;
        for (int t = 0; t < TT; t++) {
            if (idx[b * TT + t] == 2) f = 1;
            g_flags[b * TT + t] = f;
        }
    }
}

// ---------------------------------------------------------------------------
// x = tok_emb[idx] + pos_emb + (is_resp ? a_emb : q_emb)
// ---------------------------------------------------------------------------
__global__ void embed_kernel(const int* __restrict__ idx,
                             const float* __restrict__ tok,
                             const float* __restrict__ qe,
                             const float* __restrict__ ae,
                             const float* __restrict__ pos) {
    int bt = blockIdx.x;
    int t  = bt & (TT - 1);
    int token = idx[bt];
    const float* emb = tok + (size_t)token * CC;
    const float* add = g_flags[bt] ? ae : qe;
    for (int i = threadIdx.x; i < CC; i += blockDim.x)
        g_x[(size_t)bt * CC + i] = emb[i] + pos[(size_t)t * CC + i] + add[i];
}

// ---------------------------------------------------------------------------
// LayerNorm: one block per row (C = 1024, 256 threads x 4 elems)
// ---------------------------------------------------------------------------
__global__ void ln_kernel(const float* __restrict__ in, float* __restrict__ out,
                          const float* __restrict__ sc, const float* __restrict__ bi) {
    int row = blockIdx.x;
    const float* xr = in + (size_t)row * CC;
    int tid = threadIdx.x, lane = tid & 31, wid = tid >> 5;
    __shared__ float red[8];
    __shared__ float s_mean, s_rstd;

    float v[4];
    float sum = 0.f;
    #pragma unroll
    for (int i = 0; i < 4; i++) { v[i] = xr[tid + i * 256]; sum += v[i]; }
    sum = warpSum(sum);
    if (lane == 0) red[wid] = sum;
    __syncthreads();
    if (wid == 0) {
        float t = (lane < 8) ? red[lane] : 0.f;
        t = warpSum(t);
        if (lane == 0) s_mean = t * (1.0f / CC);
    }
    __syncthreads();
    float mean = s_mean;
    float sq = 0.f;
    #pragma unroll
    for (int i = 0; i < 4; i++) { float d = v[i] - mean; sq += d * d; }
    __syncthreads();
    sq = warpSum(sq);
    if (lane == 0) red[wid] = sq;
    __syncthreads();
    if (wid == 0) {
        float t = (lane < 8) ? red[lane] : 0.f;
        t = warpSum(t);
        if (lane == 0) s_rstd = rsqrtf(t * (1.0f / CC) + 1e-5f);
    }
    __syncthreads();
    float r = s_rstd;
    #pragma unroll
    for (int i = 0; i < 4; i++) {
        int c = tid + i * 256;
        out[(size_t)row * CC + c] = (v[i] - mean) * r * sc[c] + bi[c];
    }
}

// ---------------------------------------------------------------------------
// Attention: one block per (t, b*H), 128 threads. Two-pass softmax over
// scores held in shared memory (<= 4 KB).
// ---------------------------------------------------------------------------
__global__ void attn_kernel(const float* __restrict__ qkv, float* __restrict__ y) {
    const int t  = blockIdx.x;
    const int bh = blockIdx.y;
    const int b  = bh >> 4;     // H = 16
    const int h  = bh & 15;
    __shared__ float  sc[TT];
    __shared__ float4 qs[DD / 4];
    __shared__ float  red[4];
    __shared__ float  part[128];

    const int tid = threadIdx.x, lane = tid & 31, wid = tid >> 5;
    const float* base = qkv + (size_t)b * TT * 3 * CC;

    if (tid < DD / 4)
        qs[tid] = ((const float4*)(base + (size_t)t * 3 * CC + h * DD))[tid];
    __syncthreads();

    const int n = t + 1;
    // pass 1: scores
    for (int s = tid; s < n; s += 128) {
        const float4* kp = (const float4*)(base + (size_t)s * 3 * CC + CC + h * DD);
        float dot = 0.f;
        #pragma unroll
        for (int d = 0; d < DD / 4; d++) {
            float4 kk = kp[d]; float4 qq = qs[d];
            dot += qq.x * kk.x + qq.y * kk.y + qq.z * kk.z + qq.w * kk.w;
        }
        sc[s] = dot * 0.125f;   // 1/sqrt(64)
    }
    __syncthreads();

    // max
    float m = -1e30f;
    for (int s = tid; s < n; s += 128) m = fmaxf(m, sc[s]);
    m = warpMax(m);
    if (lane == 0) red[wid] = m;
    __syncthreads();
    m = fmaxf(fmaxf(red[0], red[1]), fmaxf(red[2], red[3]));
    __syncthreads();

    // exp + sum
    float sum = 0.f;
    for (int s = tid; s < n; s += 128) {
        float e = __expf(sc[s] - m);
        sc[s] = e;
        sum += e;
    }
    sum = warpSum(sum);
    if (lane == 0) red[wid] = sum;
    __syncthreads();
    sum = red[0] + red[1] + red[2] + red[3];
    float inv = 1.0f / sum;

    // pass 2: out[d] = sum_s p_s * v[s,d]  (two s-groups, 64 lanes of d each)
    float acc = 0.f;
    const int d = tid & 63, g = tid >> 6;
    for (int s = g; s < n; s += 2)
        acc += sc[s] * base[(size_t)s * 3 * CC + 2 * CC + h * DD + d];
    part[tid] = acc;
    __syncthreads();
    if (tid < 64)
        y[((size_t)b * TT + t) * CC + h * DD + tid] = (part[tid] + part[tid + 64]) * inv;
}

// ---------------------------------------------------------------------------
// SGEMM: C[M,N] (+)= A[M,K] @ B  with B either [K,N] (TB=false) or [N,K]
// (TB=true, i.e. A @ B^T). 64x64x16 tile, 256 threads, 4x4 microtile.
// EPI: 0 = store, 1 = C += acc, 2 = C = gelu(acc + bias), 3 = C += acc + bias
// All shapes are multiples of the tile (M=4096; N in {1024,2048,3072,32000};
// K in {1024,2048}), so no bounds checks.
// ---------------------------------------------------------------------------
template <bool TB, int EPI>
__global__ void sgemm_kernel(int M, int N, int K,
                             const float* __restrict__ A,
                             const float* __restrict__ Bm,
                             const float* __restrict__ bias,
                             float* __restrict__ Cm) {
    __shared__ float As[64 * 17];
    __shared__ float Bs[64 * 17];   // NN uses 16*64, NT uses 64*17

    const int tid = threadIdx.x;
    const int tx = tid & 15;        // 16 col groups * 4 = 64
    const int ty = tid >> 4;        // 16 row groups * 4 = 64
    const int bm = blockIdx.x * 64;
    const int bn = blockIdx.y * 64;

    float acc[4][4] = {};

    for (int k0 = 0; k0 < K; k0 += 16) {
        #pragma unroll
        for (int i = 0; i < 4; i++) {
            int id = tid + i * 256;
            int r = id >> 4, c = id & 15;
            As[r * 17 + c] = A[(size_t)(bm + r) * K + k0 + c];
            if (TB) {
                Bs[r * 17 + c] = Bm[(size_t)(bn + r) * K + k0 + c];
            } else {
                int r2 = id >> 6, c2 = id & 63;
                Bs[r2 * 64 + c2] = Bm[(size_t)(k0 + r2) * N + bn + c2];
            }
        }
        __syncthreads();

        #pragma unroll
        for (int k = 0; k < 16; k++) {
            float ra[4], rb[4];
            #pragma unroll
            for (int i = 0; i < 4; i++) ra[i] = As[(ty * 4 + i) * 17 + k];
            #pragma unroll
            for (int j = 0; j < 4; j++)
                rb[j] = TB ? Bs[(tx * 4 + j) * 17 + k] : Bs[k * 64 + tx * 4 + j];
            #pragma unroll
            for (int i = 0; i < 4; i++)
                #pragma unroll
                for (int j = 0; j < 4; j++)
                    acc[i][j] += ra[i] * rb[j];
        }
        __syncthreads();
    }

    #pragma unroll
    for (int i = 0; i < 4; i++) {
        int m = bm + ty * 4 + i;
        #pragma unroll
        for (int j = 0; j < 4; j++) {
            int nn = bn + tx * 4 + j;
            size_t o = (size_t)m * N + nn;
            float v = acc[i][j];
            if (EPI == 0) {
                Cm[o] = v;
            } else if (EPI == 1) {
                Cm[o] += v;
            } else if (EPI == 2) {
                v += bias[nn];
                Cm[o] = 0.5f * v * (1.0f + erff(v * 0.70710678118654752f));
            } else {
                Cm[o] += v + bias[nn];
            }
        }
    }
}

// ---------------------------------------------------------------------------
// Host-side orchestration
// ---------------------------------------------------------------------------
extern "C" void kernel_launch(void* const* d_in, const int* in_sizes, int n_in,
                              void* d_out, int out_size) {
    const int*   idx    = (const int*)  d_in[0];
    const float* tok    = (const float*)d_in[1];   // [V, C]
    const float* q_emb  = (const float*)d_in[2];
    const float* a_emb  = (const float*)d_in[3];
    const float* pos    = (const float*)d_in[4];   // [T, C]
    const float* ln1_s  = (const float*)d_in[5];
    const float* ln1_b  = (const float*)d_in[6];
    const float* attn_w = (const float*)d_in[7];   // [L, C, 3C]
    const float* proj_w = (const float*)d_in[8];   // [L, C, C]
    const float* ln2_s  = (const float*)d_in[9];
    const float* ln2_b  = (const float*)d_in[10];
    const float* mlp_w1 = (const float*)d_in[11];  // [L, C, 2C]
    const float* mlp_b1 = (const float*)d_in[12];  // [L, 2C]
    const float* mlp_w2 = (const float*)d_in[13];  // [L, 2C, C]
    const float* mlp_b2 = (const float*)d_in[14];  // [L, C]
    const float* lnf_s  = (const float*)d_in[15];
    const float* lnf_b  = (const float*)d_in[16];
    float* out = (float*)d_out;

    float *x, *h, *qkv, *y, *mlp;
    cudaGetSymbolAddress((void**)&x,   g_x);
    cudaGetSymbolAddress((void**)&h,   g_h);
    cudaGetSymbolAddress((void**)&qkv, g_qkv);
    cudaGetSymbolAddress((void**)&y,   g_y);
    cudaGetSymbolAddress((void**)&mlp, g_mlp);

    const int M = BI * TT;           // 4096 rows

    flags_kernel<<<BI, 32>>>(idx);
    embed_kernel<<<M, 256>>>(idx, tok, q_emb, a_emb, pos);

    for (int l = 0; l < LL; l++) {
        const float* aw = attn_w + (size_t)l * CC * 3 * CC;
        const float* pw = proj_w + (size_t)l * CC * CC;
        const float* w1 = mlp_w1 + (size_t)l * CC * 2 * CC;
        const float* b1 = mlp_b1 + (size_t)l * 2 * CC;
        const float* w2 = mlp_w2 + (size_t)l * 2 * CC * CC;
        const float* b2 = mlp_b2 + (size_t)l * CC;

        // h = LN1(x)
        ln_kernel<<<M, 256>>>(x, h, ln1_s + (size_t)l * CC, ln1_b + (size_t)l * CC);
        // qkv = h @ attn_w[l]           [4096,1024] @ [1024,3072]
        sgemm_kernel<false, 0><<<dim3(M / 64, 3 * CC / 64), 256>>>(M, 3 * CC, CC, h, aw, nullptr, qkv);
        // y = attention(qkv)
        attn_kernel<<<dim3(TT, BI * HH), 128>>>(qkv, y);
        // x += y @ proj_w[l]            [4096,1024] @ [1024,1024]
        sgemm_kernel<false, 1><<<dim3(M / 64, CC / 64), 256>>>(M, CC, CC, y, pw, nullptr, x);
        // h = LN2(x)
        ln_kernel<<<M, 256>>>(x, h, ln2_s + (size_t)l * CC, ln2_b + (size_t)l * CC);
        // mlp = gelu(h @ w1 + b1)       [4096,1024] @ [1024,2048]
        sgemm_kernel<false, 2><<<dim3(M / 64, 2 * CC / 64), 256>>>(M, 2 * CC, CC, h, w1, b1, mlp);
        // x += mlp @ w2 + b2            [4096,2048] @ [2048,1024]
        sgemm_kernel<false, 3><<<dim3(M / 64, CC / 64), 256>>>(M, CC, 2 * CC, mlp, w2, b2, x);
    }

    // h = LNf(x)
    ln_kernel<<<M, 256>>>(x, h, lnf_s, lnf_b);
    // logits = h @ tok^T                [4096,1024] @ [32000,1024]^T
    sgemm_kernel<true, 0><<<dim3(M / 64, VV / 64), 256>>>(M, VV, CC, h, tok, nullptr, out);
}